// round 8
// baseline (speedup 1.0000x reference)
#include <cuda_runtime.h>
#include <math.h>

#define SIZE 512
#define NB 16
#define L 1534
#define NC 16
#define O1 1023
#define O2 512
#define BN_EPS 1e-3f

// ---------------- scratch (no allocations allowed) ----------------
__device__ float g_h1[NB * 1024];            // [b][o] (o padded to 1024)
__device__ float g_h2[NB * O2];              // [b][o2]

// packed fp32x2 FMA (sm_103a FFMA2 path)
__device__ __forceinline__ void ffma2(unsigned long long &acc,
                                      unsigned long long a,
                                      unsigned long long w) {
    asm("fma.rn.f32x2 %0, %1, %2, %0;" : "+l"(acc) : "l"(a), "l"(w));
}

// =====================================================================
// Kernel 1: stage-1, coalesced register-tiled, occupancy-2 version.
// grid (128 o-tiles, 2 batch-halves), block 256 = 8 warps.
// Warp  w: sh = w&3 (4-way s-split, 4 rows each), bg = w>>2 (2 batch quads).
// Lane  : c4 = lane&3 (float4 channel quad), dr = (lane>>2)&3 (row),
//         bl = lane>>4 (batch LSB).
// Per-thread tile: 8 o x 2 b  -> block covers 8 o x 8 b.
// Every warp-wide load covers contiguous 256B halves (2-3 L1 lines).
// Rows d = sh*4 + dr + 16*i, i = 0..32; i=1..31 are predicate-free.
// =====================================================================
__global__ __launch_bounds__(256, 2) void k_stage1(const float* __restrict__ x,
                                                   const float* __restrict__ W1,
                                                   const float* __restrict__ b1) {
    const int t    = threadIdx.x;
    const int lane = t & 31;
    const int w    = t >> 5;
    const int sh   = w & 3;
    const int bg   = w >> 2;
    const int c4   = lane & 3;
    const int dr   = (lane >> 2) & 3;
    const int bl   = lane >> 4;
    const int o0   = blockIdx.x * 8;
    const int bbase = blockIdx.y * 8;

    unsigned long long acc[8][2];
    #pragma unroll
    for (int oo = 0; oo < 8; oo++)
        #pragma unroll
        for (int bb = 0; bb < 2; bb++) acc[oo][bb] = 0ull;

    // weight base: W1[o][s][c] @ o*SIZE*NC + s*NC + c ; s = d - oo, d = d0 + dr
    const float* wb[8];
    #pragma unroll
    for (int oo = 0; oo < 8; oo++) {
        const int og = min(o0 + oo, O1 - 1);          // o=1023 is a dead output
        wb[oo] = W1 + (og * SIZE + dr - oo) * NC + c4 * 4;
    }
    // x base: x[b][r][c] @ (b*L + r)*NC + c ; r = o0 + d0 + dr
    const float* xb[2];
    #pragma unroll
    for (int bb = 0; bb < 2; bb++) {
        const int b = bbase + bg * 4 + bb * 2 + bl;
        xb[bb] = x + (b * L + o0 + dr) * NC + c4 * 4;
    }

    // ---- i = 0 : d = sh*4 + dr in [0,16); weight valid iff d >= oo ----
    {
        const int d0 = sh * 4;
        const int d  = d0 + dr;
        ulonglong2 wv[8], xv[2];
        #pragma unroll
        for (int oo = 0; oo < 8; oo++) {
            ulonglong2 z; z.x = 0ull; z.y = 0ull;
            wv[oo] = (d >= oo)
                   ? *reinterpret_cast<const ulonglong2*>(wb[oo] + d0 * NC) : z;
        }
        #pragma unroll
        for (int bb = 0; bb < 2; bb++)
            xv[bb] = *reinterpret_cast<const ulonglong2*>(xb[bb] + d0 * NC);
        #pragma unroll
        for (int oo = 0; oo < 8; oo++)
            #pragma unroll
            for (int bb = 0; bb < 2; bb++) {
                ffma2(acc[oo][bb], xv[bb].x, wv[oo].x);
                ffma2(acc[oo][bb], xv[bb].y, wv[oo].y);
            }
    }

    // ---- i = 1..31 : fully valid, predicate-free ----
    #pragma unroll 4
    for (int i = 1; i < 32; i++) {
        const int off = (sh * 4 + (i << 4)) * NC;
        ulonglong2 wv[8], xv[2];
        #pragma unroll
        for (int oo = 0; oo < 8; oo++)
            wv[oo] = *reinterpret_cast<const ulonglong2*>(wb[oo] + off);
        #pragma unroll
        for (int bb = 0; bb < 2; bb++)
            xv[bb] = *reinterpret_cast<const ulonglong2*>(xb[bb] + off);
        #pragma unroll
        for (int oo = 0; oo < 8; oo++)
            #pragma unroll
            for (int bb = 0; bb < 2; bb++) {
                ffma2(acc[oo][bb], xv[bb].x, wv[oo].x);
                ffma2(acc[oo][bb], xv[bb].y, wv[oo].y);
            }
    }

    // ---- i = 32 : d in [512,520) (sh<2 only); weight valid iff d-oo<=511;
    //      x row may exceed 1533 (feeds only the dead o=1023 output) ----
    if (sh < 2) {
        const int d0 = sh * 4 + 512;
        const int d  = d0 + dr;
        const bool xok = (o0 + d) < L;
        ulonglong2 wv[8], xv[2];
        #pragma unroll
        for (int oo = 0; oo < 8; oo++) {
            ulonglong2 z; z.x = 0ull; z.y = 0ull;
            wv[oo] = (d - oo <= 511)
                   ? *reinterpret_cast<const ulonglong2*>(wb[oo] + d0 * NC) : z;
        }
        #pragma unroll
        for (int bb = 0; bb < 2; bb++) {
            ulonglong2 z; z.x = 0ull; z.y = 0ull;
            xv[bb] = xok
                   ? *reinterpret_cast<const ulonglong2*>(xb[bb] + d0 * NC) : z;
        }
        #pragma unroll
        for (int oo = 0; oo < 8; oo++)
            #pragma unroll
            for (int bb = 0; bb < 2; bb++) {
                ffma2(acc[oo][bb], xv[bb].x, wv[oo].x);
                ffma2(acc[oo][bb], xv[bb].y, wv[oo].y);
            }
    }

    // ---- reduction: c4 and dr lane dims are both reduction dims ----
    float v[8][2];
    #pragma unroll
    for (int oo = 0; oo < 8; oo++)
        #pragma unroll
        for (int bb = 0; bb < 2; bb++) {
            float2 f = *reinterpret_cast<float2*>(&acc[oo][bb]);
            v[oo][bb] = f.x + f.y;
        }
    #pragma unroll
    for (int mask = 1; mask <= 8; mask <<= 1)
        #pragma unroll
        for (int oo = 0; oo < 8; oo++)
            #pragma unroll
            for (int bb = 0; bb < 2; bb++)
                v[oo][bb] += __shfl_xor_sync(0xffffffffu, v[oo][bb], mask);

    __shared__ float sm[4][2][2][2][8];   // [sh][bg][bl][bb][oo]
    if ((lane & 15) == 0) {
        #pragma unroll
        for (int oo = 0; oo < 8; oo++)
            #pragma unroll
            for (int bb = 0; bb < 2; bb++)
                sm[sh][bg][bl][bb][oo] = v[oo][bb];
    }
    __syncthreads();

    if (t < 64) {
        const int ol = t >> 3;
        const int bi = t & 7;             // bi = bg*4 + bb*2 + bl
        const int bg2 = bi >> 2;
        const int bb2 = (bi >> 1) & 1;
        const int bl2 = bi & 1;
        float s = sm[0][bg2][bl2][bb2][ol] + sm[1][bg2][bl2][bb2][ol]
                + sm[2][bg2][bl2][bb2][ol] + sm[3][bg2][bl2][bb2][ol];
        const int o = o0 + ol;
        if (o < O1) {
            s += b1[o];
            g_h1[(bbase + bi) * 1024 + o] = (s > 0.f) ? s : expm1f(s);  // ELU
        }
    }
}

// =====================================================================
// Kernel 2: stage-2  h2[b,o2] = sum_s h1[b,o2+s] * W2[o2,s] + b2[o2]
// grid 128 (4 o2 per block), block 256 (64-way s split)
// =====================================================================
__global__ __launch_bounds__(256) void k_stage2(const float* __restrict__ W2,
                                                const float* __restrict__ b2) {
    const int t   = threadIdx.x;
    const int ol  = t >> 6;
    const int l64 = t & 63;
    const int o2  = blockIdx.x * 4 + ol;

    float acc[NB];
    #pragma unroll
    for (int b = 0; b < NB; b++) acc[b] = 0.f;

    #pragma unroll
    for (int i = 0; i < 8; i++) {
        const int s = l64 + (i << 6);
        const float w = W2[o2 * SIZE + s];
        #pragma unroll
        for (int b = 0; b < NB; b++)
            acc[b] = fmaf(g_h1[b * 1024 + o2 + s], w, acc[b]);
    }

    __shared__ float red[4 * 64 * 17];
    #pragma unroll
    for (int b = 0; b < NB; b++)
        red[ol * 1088 + l64 * 17 + b] = acc[b];
    __syncthreads();

    if (t < 64) {
        const int olr = t >> 4;
        const int b   = t & 15;
        float s = 0.f;
        #pragma unroll
        for (int j = 0; j < 64; j++)
            s += red[olr * 1088 + j * 17 + b];
        const int o2g = blockIdx.x * 4 + olr;
        g_h2[b * O2 + o2g] = s + b2[o2g];
    }
}

// =====================================================================
// Kernel 3: gate g[b] = (h2.Wl + bl) * sigmoid(h2.Ws + bs), then
// out[b,l,c] = ((xpad + g) - mean)*rsqrt(var+eps)*gamma + beta
// grid (16 b, 12 row-chunks of 128), block 256. Gate recomputed per block.
// =====================================================================
__global__ __launch_bounds__(256) void k_out(const float* __restrict__ x,
                                             const float* __restrict__ Wl,
                                             const float* __restrict__ bl,
                                             const float* __restrict__ Ws,
                                             const float* __restrict__ bs,
                                             const float* __restrict__ gamma,
                                             const float* __restrict__ beta,
                                             const float* __restrict__ mean,
                                             const float* __restrict__ var,
                                             float* __restrict__ out) {
    const int b  = blockIdx.x;
    const int cb = blockIdx.y;
    const int t  = threadIdx.x;

    // gate reduction (512-elem dots, 2 elems/thread)
    float h2a = g_h2[b * O2 + t];
    float h2b = g_h2[b * O2 + 256 + t];
    float aL = h2a * Wl[t] + h2b * Wl[256 + t];
    float aS = h2a * Ws[t] + h2b * Ws[256 + t];
    #pragma unroll
    for (int off = 16; off; off >>= 1) {
        aL += __shfl_down_sync(0xffffffffu, aL, off);
        aS += __shfl_down_sync(0xffffffffu, aS, off);
    }
    __shared__ float rL[8], rS[8];
    __shared__ float sa[16], sd[16];
    __shared__ float gsh;
    if ((t & 31) == 0) { rL[t >> 5] = aL; rS[t >> 5] = aS; }
    __syncthreads();
    if (t == 0) {
        float sL = 0.f, sS = 0.f;
        #pragma unroll
        for (int j = 0; j < 8; j++) { sL += rL[j]; sS += rS[j]; }
        sL += bl[0]; sS += bs[0];
        gsh = sL * (1.f / (1.f + expf(-sS)));
    }
    __syncthreads();
    if (t < 16) {
        float sc = gamma[t] * rsqrtf(var[t] + BN_EPS);
        sa[t] = sc;
        sd[t] = beta[t] - mean[t] * sc + gsh * sc;   // folds gate + BN shift
    }
    __syncthreads();

    const int row0 = cb * 128;
    const int rows = min(128, 1535 - row0);
    const float4* x4 = reinterpret_cast<const float4*>(x);
    float4* o4 = reinterpret_cast<float4*>(out);
    #pragma unroll 2
    for (int j = t; j < rows * 4; j += 256) {
        const int l  = row0 + (j >> 2);
        const int c4 = j & 3;
        float4 xv; xv.x = 0.f; xv.y = 0.f; xv.z = 0.f; xv.w = 0.f;
        if (l < L) xv = x4[(b * L + l) * 4 + c4];
        float4 r;
        const int c = c4 * 4;
        r.x = xv.x * sa[c + 0] + sd[c + 0];
        r.y = xv.y * sa[c + 1] + sd[c + 1];
        r.z = xv.z * sa[c + 2] + sd[c + 2];
        r.w = xv.w * sa[c + 3] + sd[c + 3];
        o4[(b * 1535 + l) * 4 + c4] = r;
    }
}

// =====================================================================
extern "C" void kernel_launch(void* const* d_in, const int* in_sizes, int n_in,
                              void* d_out, int out_size) {
    const float* x     = (const float*)d_in[0];
    const float* W1    = (const float*)d_in[1];
    const float* b1    = (const float*)d_in[2];
    const float* W2    = (const float*)d_in[3];
    const float* b2    = (const float*)d_in[4];
    const float* Wl    = (const float*)d_in[5];
    const float* bl    = (const float*)d_in[6];
    const float* Ws    = (const float*)d_in[7];
    const float* bs    = (const float*)d_in[8];
    const float* gamma = (const float*)d_in[9];
    const float* beta  = (const float*)d_in[10];
    const float* mean  = (const float*)d_in[11];
    const float* var   = (const float*)d_in[12];
    float* out = (float*)d_out;

    k_stage1<<<dim3(128, 2), 256>>>(x, W1, b1);
    k_stage2<<<128, 256>>>(W2, b2);
    k_out<<<dim3(16, 12), 256>>>(x, Wl, bl, Ws, bs, gamma, beta, mean, var, out);
}

// round 11
// speedup vs baseline: 1.0696x; 1.0696x over previous
#include <cuda_runtime.h>
#include <math.h>

#define SIZE 512
#define NB 16
#define L 1534
#define NC 16
#define O1 1023
#define O2 512
#define BN_EPS 1e-3f
#define NSTAGE 4

// ---------------- scratch (no allocations allowed) ----------------
__device__ float g_h1[NB * 1024];            // [b][o] (o padded to 1024)
__device__ float g_h2[NB * O2];              // [b][o2]

// packed fp32x2 FMA (sm_103a FFMA2 path)
__device__ __forceinline__ void ffma2(unsigned long long &acc,
                                      unsigned long long a,
                                      unsigned long long w) {
    asm("fma.rn.f32x2 %0, %1, %2, %0;" : "+l"(acc) : "l"(a), "l"(w));
}

__device__ __forceinline__ void cp_async16(unsigned dst, const void* src) {
    asm volatile("cp.async.cg.shared.global [%0], [%1], 16;"
                 :: "r"(dst), "l"(src));
}
__device__ __forceinline__ void cp_commit() {
    asm volatile("cp.async.commit_group;");
}
__device__ __forceinline__ void cp_wait2() {
    asm volatile("cp.async.wait_group 2;");
}

// =====================================================================
// Kernel 1: stage-1 with W1 staged through a 4-deep cp.async smem
// pipeline (interior iters) + x register double-buffer.
// grid 128 (8-o tiles), block 256 = 8 warps.
// Warp  w: sh = w&3 (4-way d-split within a 16-row iter), bg = w>>2.
// Lane  : c4 = lane&3 (float4 channel quad), dr = (lane>>2)&3 (row),
//         bl = lane>>4 (batch LSB).
// Per-thread tile: 8 o x 4 b (x2 b in lanes) -> block = 8 o x 16 b.
// Rows d = sh*4 + dr + 16*i, i = 0..32; i=1..31 are predicate-free and
// read W1 from smem; i=0 / i=32 use the predicated global path.
// =====================================================================
__global__ __launch_bounds__(256, 1) void k_stage1(const float* __restrict__ x,
                                                   const float* __restrict__ W1,
                                                   const float* __restrict__ b1) {
    const int t    = threadIdx.x;
    const int lane = t & 31;
    const int w    = t >> 5;
    const int sh   = w & 3;
    const int bg   = w >> 2;
    const int c4   = lane & 3;
    const int dr   = (lane >> 2) & 3;
    const int bl   = lane >> 4;
    const int o0   = blockIdx.x * 8;

    // W stage buffers: [stage][oo][d_local 0..15][c 0..15] floats = 8KB/stage
    __shared__ float ws[NSTAGE * 2048];
    __shared__ float sm[4][2][2][4][8];   // [sh][bg][bl][bb][oo] reduction

    // ---- cp.async thread mapping: 512 16B-chunks/stage, 2 per thread ----
    const float* csrc[2];
    unsigned     coff[2];
    #pragma unroll
    for (int j = 0; j < 2; j++) {
        const int k  = t + j * 256;
        const int oo = k >> 6;
        const int dl = (k >> 2) & 15;
        const int cc = k & 3;
        const int og = min(o0 + oo, O1 - 1);
        // s = i*16 + dl - oo ; for i in [1,31] this is always in [9,511]
        csrc[j] = W1 + ((og * SIZE + dl - oo) * NC + cc * 4);
        coff[j] = (unsigned)((oo * 16 + dl) * 64 + cc * 16);
    }
    const unsigned wsb = (unsigned)__cvta_generic_to_shared(ws);

    unsigned long long acc[8][4];
    #pragma unroll
    for (int oo = 0; oo < 8; oo++)
        #pragma unroll
        for (int bb = 0; bb < 4; bb++) acc[oo][bb] = 0ull;

    // weight base (global path, edge iters): s = d - oo, d = d0 + dr
    const float* wb[8];
    #pragma unroll
    for (int oo = 0; oo < 8; oo++) {
        const int og = min(o0 + oo, O1 - 1);          // o=1023 is a dead output
        wb[oo] = W1 + (og * SIZE + dr - oo) * NC + c4 * 4;
    }
    // x base: r = o0 + d0 + dr
    const float* xb[4];
    #pragma unroll
    for (int bb = 0; bb < 4; bb++) {
        const int b = bg * 8 + bb * 2 + bl;
        xb[bb] = x + (b * L + o0 + dr) * NC + c4 * 4;
    }

    // ---- prologue: prefetch W stages for i = 1,2,3 ----
    #pragma unroll
    for (int p = 1; p <= 3; p++) {
        const unsigned base = wsb + (unsigned)((p & 3) * 8192);
        cp_async16(base + coff[0], csrc[0] + p * 256);
        cp_async16(base + coff[1], csrc[1] + p * 256);
        cp_commit();
    }

    // ---- i = 0 : d = sh*4 + dr in [0,16); weight valid iff d >= oo ----
    {
        const int d0 = sh * 4;
        const int d  = d0 + dr;
        ulonglong2 wv[8], xv[4];
        #pragma unroll
        for (int oo = 0; oo < 8; oo++) {
            ulonglong2 z; z.x = 0ull; z.y = 0ull;
            wv[oo] = (d >= oo)
                   ? *reinterpret_cast<const ulonglong2*>(wb[oo] + d0 * NC) : z;
        }
        #pragma unroll
        for (int bb = 0; bb < 4; bb++)
            xv[bb] = *reinterpret_cast<const ulonglong2*>(xb[bb] + d0 * NC);
        #pragma unroll
        for (int oo = 0; oo < 8; oo++)
            #pragma unroll
            for (int bb = 0; bb < 4; bb++) {
                ffma2(acc[oo][bb], xv[bb].x, wv[oo].x);
                ffma2(acc[oo][bb], xv[bb].y, wv[oo].y);
            }
    }

    // ---- x register double-buffer: load xv for i = 1 ----
    ulonglong2 xc[4];
    {
        const int off = (sh * 4 + 16) * NC;
        #pragma unroll
        for (int bb = 0; bb < 4; bb++)
            xc[bb] = *reinterpret_cast<const ulonglong2*>(xb[bb] + off);
    }

    // ---- i = 1..31 : W from smem pipeline, x double-buffered ----
    for (int i = 1; i < 32; i++) {
        cp_wait2();          // group for stage i has landed (for every thread)
        __syncthreads();     // ...and is visible; slot (i-1)&3 is free to refill

        if (i + 3 < 32) {    // prefetch stage i+3 into slot (i+3)&3 = (i-1)&3
            const unsigned base = wsb + (unsigned)(((i + 3) & 3) * 8192);
            cp_async16(base + coff[0], csrc[0] + (i + 3) * 256);
            cp_async16(base + coff[1], csrc[1] + (i + 3) * 256);
        }
        cp_commit();         // commit (possibly empty) to keep accounting fixed

        // prefetch x for i+1
        ulonglong2 xn[4];
        if (i < 31) {
            const int off = (sh * 4 + (i + 1) * 16) * NC;
            #pragma unroll
            for (int bb = 0; bb < 4; bb++)
                xn[bb] = *reinterpret_cast<const ulonglong2*>(xb[bb] + off);
        }

        // compute iter i from smem
        const float* wsf = ws + (i & 3) * 2048;
        ulonglong2 wv[8];
        #pragma unroll
        for (int oo = 0; oo < 8; oo++)
            wv[oo] = *reinterpret_cast<const ulonglong2*>(
                         wsf + (oo * 16 + sh * 4 + dr) * 16 + c4 * 4);
        #pragma unroll
        for (int oo = 0; oo < 8; oo++)
            #pragma unroll
            for (int bb = 0; bb < 4; bb++) {
                ffma2(acc[oo][bb], xc[bb].x, wv[oo].x);
                ffma2(acc[oo][bb], xc[bb].y, wv[oo].y);
            }
        #pragma unroll
        for (int bb = 0; bb < 4; bb++) xc[bb] = xn[bb];
    }

    // ---- i = 32 : d in [512,520) (sh<2 only); weight valid iff d-oo<=511;
    //      x row may exceed 1533 (feeds only the dead o=1023 output) ----
    if (sh < 2) {
        const int d0 = sh * 4 + 512;
        const int d  = d0 + dr;
        const bool xok = (o0 + d) < L;
        ulonglong2 wv[8], xv[4];
        #pragma unroll
        for (int oo = 0; oo < 8; oo++) {
            ulonglong2 z; z.x = 0ull; z.y = 0ull;
            wv[oo] = (d - oo <= 511)
                   ? *reinterpret_cast<const ulonglong2*>(wb[oo] + d0 * NC) : z;
        }
        #pragma unroll
        for (int bb = 0; bb < 4; bb++) {
            ulonglong2 z; z.x = 0ull; z.y = 0ull;
            xv[bb] = xok
                   ? *reinterpret_cast<const ulonglong2*>(xb[bb] + d0 * NC) : z;
        }
        #pragma unroll
        for (int oo = 0; oo < 8; oo++)
            #pragma unroll
            for (int bb = 0; bb < 4; bb++) {
                ffma2(acc[oo][bb], xv[bb].x, wv[oo].x);
                ffma2(acc[oo][bb], xv[bb].y, wv[oo].y);
            }
    }

    // ---- reduction: c4 and dr lane dims are both reduction dims ----
    float v[8][4];
    #pragma unroll
    for (int oo = 0; oo < 8; oo++)
        #pragma unroll
        for (int bb = 0; bb < 4; bb++) {
            float2 f = *reinterpret_cast<float2*>(&acc[oo][bb]);
            v[oo][bb] = f.x + f.y;
        }
    #pragma unroll
    for (int mask = 1; mask <= 8; mask <<= 1)
        #pragma unroll
        for (int oo = 0; oo < 8; oo++)
            #pragma unroll
            for (int bb = 0; bb < 4; bb++)
                v[oo][bb] += __shfl_xor_sync(0xffffffffu, v[oo][bb], mask);

    if ((lane & 15) == 0) {
        #pragma unroll
        for (int oo = 0; oo < 8; oo++)
            #pragma unroll
            for (int bb = 0; bb < 4; bb++)
                sm[sh][bg][bl][bb][oo] = v[oo][bb];
    }
    __syncthreads();

    if (t < 128) {
        const int ol  = t >> 4;
        const int b   = t & 15;
        const int bg2 = b >> 3;
        const int bb2 = (b & 7) >> 1;
        const int bl2 = b & 1;
        float s = sm[0][bg2][bl2][bb2][ol] + sm[1][bg2][bl2][bb2][ol]
                + sm[2][bg2][bl2][bb2][ol] + sm[3][bg2][bl2][bb2][ol];
        const int o = o0 + ol;
        if (o < O1) {
            s += b1[o];
            g_h1[b * 1024 + o] = (s > 0.f) ? s : expm1f(s);   // ELU(alpha=1)
        }
    }
}

// =====================================================================
// Kernel 2: stage-2  h2[b,o2] = sum_s h1[b,o2+s] * W2[o2,s] + b2[o2]
// grid 128 (4 o2 per block), block 256 (64-way s split)
// =====================================================================
__global__ __launch_bounds__(256) void k_stage2(const float* __restrict__ W2,
                                                const float* __restrict__ b2) {
    const int t   = threadIdx.x;
    const int ol  = t >> 6;
    const int l64 = t & 63;
    const int o2  = blockIdx.x * 4 + ol;

    float acc[NB];
    #pragma unroll
    for (int b = 0; b < NB; b++) acc[b] = 0.f;

    #pragma unroll
    for (int i = 0; i < 8; i++) {
        const int s = l64 + (i << 6);
        const float w = W2[o2 * SIZE + s];
        #pragma unroll
        for (int b = 0; b < NB; b++)
            acc[b] = fmaf(g_h1[b * 1024 + o2 + s], w, acc[b]);
    }

    __shared__ float red[4 * 64 * 17];
    #pragma unroll
    for (int b = 0; b < NB; b++)
        red[ol * 1088 + l64 * 17 + b] = acc[b];
    __syncthreads();

    if (t < 64) {
        const int olr = t >> 4;
        const int b   = t & 15;
        float s = 0.f;
        #pragma unroll
        for (int j = 0; j < 64; j++)
            s += red[olr * 1088 + j * 17 + b];
        const int o2g = blockIdx.x * 4 + olr;
        g_h2[b * O2 + o2g] = s + b2[o2g];
    }
}

// =====================================================================
// Kernel 3: gate g[b] = (h2.Wl + bl) * sigmoid(h2.Ws + bs), then
// out[b,l,c] = ((xpad + g) - mean)*rsqrt(var+eps)*gamma + beta
// grid (16 b, 12 row-chunks of 128), block 256. Gate recomputed per block.
// =====================================================================
__global__ __launch_bounds__(256) void k_out(const float* __restrict__ x,
                                             const float* __restrict__ Wl,
                                             const float* __restrict__ bl,
                                             const float* __restrict__ Ws,
                                             const float* __restrict__ bs,
                                             const float* __restrict__ gamma,
                                             const float* __restrict__ beta,
                                             const float* __restrict__ mean,
                                             const float* __restrict__ var,
                                             float* __restrict__ out) {
    const int b  = blockIdx.x;
    const int cb = blockIdx.y;
    const int t  = threadIdx.x;

    // gate reduction (512-elem dots, 2 elems/thread)
    float h2a = g_h2[b * O2 + t];
    float h2b = g_h2[b * O2 + 256 + t];
    float aL = h2a * Wl[t] + h2b * Wl[256 + t];
    float aS = h2a * Ws[t] + h2b * Ws[256 + t];
    #pragma unroll
    for (int off = 16; off; off >>= 1) {
        aL += __shfl_down_sync(0xffffffffu, aL, off);
        aS += __shfl_down_sync(0xffffffffu, aS, off);
    }
    __shared__ float rL[8], rS[8];
    __shared__ float sa[16], sd[16];
    __shared__ float gsh;
    if ((t & 31) == 0) { rL[t >> 5] = aL; rS[t >> 5] = aS; }
    __syncthreads();
    if (t == 0) {
        float sL = 0.f, sS = 0.f;
        #pragma unroll
        for (int j = 0; j < 8; j++) { sL += rL[j]; sS += rS[j]; }
        sL += bl[0]; sS += bs[0];
        gsh = sL * (1.f / (1.f + expf(-sS)));
    }
    __syncthreads();
    if (t < 16) {
        float sc = gamma[t] * rsqrtf(var[t] + BN_EPS);
        sa[t] = sc;
        sd[t] = beta[t] - mean[t] * sc + gsh * sc;   // folds gate + BN shift
    }
    __syncthreads();

    const int row0 = cb * 128;
    const int rows = min(128, 1535 - row0);
    const float4* x4 = reinterpret_cast<const float4*>(x);
    float4* o4 = reinterpret_cast<float4*>(out);
    #pragma unroll 2
    for (int j = t; j < rows * 4; j += 256) {
        const int l  = row0 + (j >> 2);
        const int c4 = j & 3;
        float4 xv; xv.x = 0.f; xv.y = 0.f; xv.z = 0.f; xv.w = 0.f;
        if (l < L) xv = x4[(b * L + l) * 4 + c4];
        float4 r;
        const int c = c4 * 4;
        r.x = xv.x * sa[c + 0] + sd[c + 0];
        r.y = xv.y * sa[c + 1] + sd[c + 1];
        r.z = xv.z * sa[c + 2] + sd[c + 2];
        r.w = xv.w * sa[c + 3] + sd[c + 3];
        o4[(b * 1535 + l) * 4 + c4] = r;
    }
}

// =====================================================================
extern "C" void kernel_launch(void* const* d_in, const int* in_sizes, int n_in,
                              void* d_out, int out_size) {
    const float* x     = (const float*)d_in[0];
    const float* W1    = (const float*)d_in[1];
    const float* b1    = (const float*)d_in[2];
    const float* W2    = (const float*)d_in[3];
    const float* b2    = (const float*)d_in[4];
    const float* Wl    = (const float*)d_in[5];
    const float* bl    = (const float*)d_in[6];
    const float* Ws    = (const float*)d_in[7];
    const float* bs    = (const float*)d_in[8];
    const float* gamma = (const float*)d_in[9];
    const float* beta  = (const float*)d_in[10];
    const float* mean  = (const float*)d_in[11];
    const float* var   = (const float*)d_in[12];
    float* out = (float*)d_out;

    k_stage1<<<128, 256>>>(x, W1, b1);
    k_stage2<<<128, 256>>>(W2, b2);
    k_out<<<dim3(16, 12), 256>>>(x, Wl, bl, Ws, bs, gamma, beta, mean, var, out);
}